// round 1
// baseline (speedup 1.0000x reference)
#include <cuda_runtime.h>
#include <math.h>

// Problem dims
#define SS 50
#define LL 1024
#define DD 768
#define DD4 192

// ---------------- static scratch (alloc-free rule) ----------------
__device__ float g_bufA[(size_t)SS * LL * DD];
__device__ float g_bufB[(size_t)SS * LL * DD];
__device__ float g_bufC[(size_t)SS * LL * DD];
__device__ float g_q[(size_t)SS * LL * DD4];
__device__ float g_k[(size_t)SS * LL * DD4];
__device__ float g_scores[(size_t)SS * LL * LL];

// ---------------- generic tiled SGEMM ----------------
// C[b] = A[b] @ B[b] (+bias[b]) (+relu)
// A: [M,K] row-major. B: NN -> [K,N]; NT -> [N,K] (computes A @ B^T).
// Per-batch element strides sA, sB, sBias, sC.
template<bool TRANSB, bool BIAS, bool RELU>
__global__ __launch_bounds__(256)
void sgemm_kernel(const float* __restrict__ Ab, const float* __restrict__ Bb,
                  const float* __restrict__ biasb, float* __restrict__ Cb,
                  int M, int N, int K,
                  long sA, long sB, long sBias, long sC)
{
    const int BM = 128, BN = 128, BK = 8, TM = 8, TN = 8;
    __shared__ float As[BK][BM];
    __shared__ float Bs[BK][BN];

    const int b = blockIdx.z;
    const float* A = Ab + (long)b * sA;
    const float* B = Bb + (long)b * sB;
    float* C = Cb + (long)b * sC;

    const int block_row = blockIdx.y * BM;
    const int block_col = blockIdx.x * BN;
    const int tid = threadIdx.x;          // 256 threads
    const int tr = tid / 16;              // 0..15
    const int tc = tid % 16;              // 0..15

    float acc[TM][TN];
    #pragma unroll
    for (int i = 0; i < TM; i++)
        #pragma unroll
        for (int j = 0; j < TN; j++)
            acc[i][j] = 0.0f;

    float ra[TM], rb[TN];

    for (int k0 = 0; k0 < K; k0 += BK) {
        // Load A tile: BM x BK = 1024 elems, 4 per thread
        #pragma unroll
        for (int i = 0; i < 4; i++) {
            int idx = tid + i * 256;
            int r = idx / BK, c = idx % BK;
            int gr = block_row + r, gc = k0 + c;
            As[c][r] = (gr < M && gc < K) ? A[(long)gr * K + gc] : 0.0f;
        }
        // Load B tile: BK x BN = 1024 elems, 4 per thread
        if (TRANSB) {
            #pragma unroll
            for (int i = 0; i < 4; i++) {
                int idx = tid + i * 256;
                int n = idx / BK, kk = idx % BK;   // contiguous kk -> coalesced-ish
                int gn = block_col + n, gk = k0 + kk;
                Bs[kk][n] = (gn < N && gk < K) ? B[(long)gn * K + gk] : 0.0f;
            }
        } else {
            #pragma unroll
            for (int i = 0; i < 4; i++) {
                int idx = tid + i * 256;
                int r = idx / BN, c = idx % BN;
                int gk = k0 + r, gn = block_col + c;
                Bs[r][c] = (gk < K && gn < N) ? B[(long)gk * N + gn] : 0.0f;
            }
        }
        __syncthreads();

        #pragma unroll
        for (int kk = 0; kk < BK; kk++) {
            #pragma unroll
            for (int i = 0; i < TM; i++) ra[i] = As[kk][tr * TM + i];
            #pragma unroll
            for (int j = 0; j < TN; j++) rb[j] = Bs[kk][tc * TN + j];
            #pragma unroll
            for (int i = 0; i < TM; i++)
                #pragma unroll
                for (int j = 0; j < TN; j++)
                    acc[i][j] += ra[i] * rb[j];
        }
        __syncthreads();
    }

    #pragma unroll
    for (int i = 0; i < TM; i++) {
        int gm = block_row + tr * TM + i;
        if (gm >= M) continue;
        #pragma unroll
        for (int j = 0; j < TN; j++) {
            int gn = block_col + tc * TN + j;
            if (gn >= N) continue;
            float v = acc[i][j];
            if (BIAS) v += biasb[(long)b * sBias + gn];
            if (RELU) v = fmaxf(v, 0.0f);
            C[(long)gm * N + gn] = v;
        }
    }
}

// ---------------- row softmax (with pre-scale), rows up to 1024 ----------------
__global__ __launch_bounds__(256)
void softmax_kernel(float* __restrict__ data, int n, float scale)
{
    long row = blockIdx.x;
    float* p = data + row * (long)n;
    int t = threadIdx.x;
    int w = t >> 5, lane = t & 31;

    float loc[4];
    int cnt = 0;
    float mx = -3.0e38f;
    for (int i = t; i < n; i += 256) {
        float v = p[i] * scale;
        loc[cnt++] = v;
        mx = fmaxf(mx, v);
    }
    // block max
    #pragma unroll
    for (int o = 16; o > 0; o >>= 1) mx = fmaxf(mx, __shfl_xor_sync(0xffffffffu, mx, o));
    __shared__ float red[8];
    if (lane == 0) red[w] = mx;
    __syncthreads();
    if (t < 8) {
        float v = red[t];
        #pragma unroll
        for (int o = 4; o > 0; o >>= 1) v = fmaxf(v, __shfl_xor_sync(0xffu, v, o));
        if (t == 0) red[0] = v;
    }
    __syncthreads();
    mx = red[0];
    __syncthreads();

    float sum = 0.0f;
    for (int c = 0; c < cnt; c++) {
        float e = __expf(loc[c] - mx);
        loc[c] = e;
        sum += e;
    }
    #pragma unroll
    for (int o = 16; o > 0; o >>= 1) sum += __shfl_xor_sync(0xffffffffu, sum, o);
    if (lane == 0) red[w] = sum;
    __syncthreads();
    if (t < 8) {
        float v = red[t];
        #pragma unroll
        for (int o = 4; o > 0; o >>= 1) v += __shfl_xor_sync(0xffu, v, o);
        if (t == 0) red[0] = v;
    }
    __syncthreads();
    float inv = 1.0f / red[0];

    cnt = 0;
    for (int i = t; i < n; i += 256) p[i] = loc[cnt++] * inv;
}

// ---------------- fused residual + LayerNorm over D=768 ----------------
// out[row] = LN(resid[row] + h[row]) * gamma + beta,
// gamma/beta selected by group: offset = (row / rows_per_group) * gstride.
__global__ __launch_bounds__(256)
void ln_kernel(const float* __restrict__ resid, const float* __restrict__ h,
               const float* __restrict__ gam, const float* __restrict__ bet,
               float* __restrict__ out, int rows_per_group, int gstride)
{
    long row = blockIdx.x;
    const float* r  = resid + row * (long)DD;
    const float* hh = h     + row * (long)DD;
    long go = (long)(row / rows_per_group) * gstride;
    const float* gp = gam + go;
    const float* bp = bet + go;
    int t = threadIdx.x;
    int w = t >> 5, lane = t & 31;

    float v[3];
    float s = 0.0f, s2 = 0.0f;
    #pragma unroll
    for (int i = 0; i < 3; i++) {
        int d = t + i * 256;
        float val = r[d] + hh[d];
        v[i] = val;
        s += val;
        s2 += val * val;
    }
    #pragma unroll
    for (int o = 16; o > 0; o >>= 1) {
        s  += __shfl_xor_sync(0xffffffffu, s, o);
        s2 += __shfl_xor_sync(0xffffffffu, s2, o);
    }
    __shared__ float rs[8], rs2[8];
    if (lane == 0) { rs[w] = s; rs2[w] = s2; }
    __syncthreads();
    if (t < 8) {
        s = rs[t]; s2 = rs2[t];
        #pragma unroll
        for (int o = 4; o > 0; o >>= 1) {
            s  += __shfl_xor_sync(0xffu, s, o);
            s2 += __shfl_xor_sync(0xffu, s2, o);
        }
        if (t == 0) { rs[0] = s; rs2[0] = s2; }
    }
    __syncthreads();
    float mean = rs[0] * (1.0f / DD);
    float var  = rs2[0] * (1.0f / DD) - mean * mean;
    float inv  = rsqrtf(var + 1e-5f);

    float* op = out + row * (long)DD;
    #pragma unroll
    for (int i = 0; i < 3; i++) {
        int d = t + i * 256;
        op[d] = (v[i] - mean) * inv * gp[d] + bp[d];
    }
}

// ---------------- transpose [d0, d1, D] -> [d1, d0, D] ----------------
__global__ __launch_bounds__(256)
void transpose_kernel(const float* __restrict__ in, float* __restrict__ out,
                      int d0, int d1)
{
    long blk = blockIdx.x;
    int i = (int)(blk / d1);
    int j = (int)(blk % d1);
    const float* src = in + ((long)i * d1 + j) * DD;
    float* dst = out + ((long)j * d0 + i) * DD;
    for (int t = threadIdx.x; t < DD; t += 256) dst[t] = src[t];
}

// ---------------- launch plumbing ----------------
static inline int cdiv(int a, int b) { return (a + b - 1) / b; }

static void gemm_nn(const float* A, const float* B, float* C,
                    int M, int N, int K, int batch,
                    long sA, long sB, long sC)
{
    dim3 grid(cdiv(N, 128), cdiv(M, 128), batch);
    sgemm_kernel<false, false, false><<<grid, 256>>>(A, B, nullptr, C, M, N, K, sA, sB, 0, sC);
}
static void gemm_nt(const float* A, const float* B, float* C,
                    int M, int N, int K, int batch,
                    long sA, long sB, long sC)
{
    dim3 grid(cdiv(N, 128), cdiv(M, 128), batch);
    sgemm_kernel<true, false, false><<<grid, 256>>>(A, B, nullptr, C, M, N, K, sA, sB, 0, sC);
}
static void gemm_nn_bias(const float* A, const float* B, const float* bias, float* C,
                         int M, int N, int K, int batch,
                         long sA, long sB, long sBias, long sC, bool relu)
{
    dim3 grid(cdiv(N, 128), cdiv(M, 128), batch);
    if (relu)
        sgemm_kernel<false, true, true><<<grid, 256>>>(A, B, bias, C, M, N, K, sA, sB, sBias, sC);
    else
        sgemm_kernel<false, true, false><<<grid, 256>>>(A, B, bias, C, M, N, K, sA, sB, sBias, sC);
}

extern "C" void kernel_launch(void* const* d_in, const int* in_sizes, int n_in,
                              void* d_out, int out_size)
{
    (void)in_sizes; (void)n_in; (void)out_size;

    const float* x        = (const float*)d_in[0];
    const float* pre_Wq   = (const float*)d_in[1];
    const float* pre_Wk   = (const float*)d_in[2];
    const float* pre_Wv   = (const float*)d_in[3];
    const float* ln1_g    = (const float*)d_in[4];
    const float* ln1_b    = (const float*)d_in[5];
    const float* pre_W1   = (const float*)d_in[6];
    const float* pre_b1   = (const float*)d_in[7];
    const float* pre_W2   = (const float*)d_in[8];
    const float* pre_b2   = (const float*)d_in[9];
    const float* ln4p_g   = (const float*)d_in[10];
    const float* ln4p_b   = (const float*)d_in[11];
    const float* cross_Wq = (const float*)d_in[12];
    const float* cross_Wk = (const float*)d_in[13];
    const float* cross_Wv = (const float*)d_in[14];
    const float* ln2_g    = (const float*)d_in[15];
    const float* ln2_b    = (const float*)d_in[16];
    const float* post_Wq  = (const float*)d_in[17];
    const float* post_Wk  = (const float*)d_in[18];
    const float* post_Wv  = (const float*)d_in[19];
    const float* ln3_g    = (const float*)d_in[20];
    const float* ln3_b    = (const float*)d_in[21];
    const float* post_W1  = (const float*)d_in[22];
    const float* post_b1  = (const float*)d_in[23];
    const float* post_W2  = (const float*)d_in[24];
    const float* post_b2  = (const float*)d_in[25];
    const float* ln4_g    = (const float*)d_in[26];
    const float* ln4_b    = (const float*)d_in[27];
    float* out = (float*)d_out;

    float *bufA, *bufB, *bufC, *q, *k, *scores;
    cudaGetSymbolAddress((void**)&bufA, g_bufA);
    cudaGetSymbolAddress((void**)&bufB, g_bufB);
    cudaGetSymbolAddress((void**)&bufC, g_bufC);
    cudaGetSymbolAddress((void**)&q, g_q);
    cudaGetSymbolAddress((void**)&k, g_k);
    cudaGetSymbolAddress((void**)&scores, g_scores);

    const float scale = 1.0f / sqrtf((float)DD4);
    const long LD  = (long)LL * DD;
    const long LD4 = (long)LL * DD4;
    const long SD  = (long)SS * DD;
    const long SD4 = (long)SS * DD4;

    // ================= pre_self_step attention =================
    gemm_nn(x, pre_Wq, q, LL, DD4, DD, SS, LD, (long)DD * DD4, LD4);
    gemm_nn(x, pre_Wk, k, LL, DD4, DD, SS, LD, (long)DD * DD4, LD4);
    gemm_nt(q, k, scores, LL, LL, DD4, SS, LD4, LD4, (long)LL * LL);
    softmax_kernel<<<SS * LL, 256>>>(scores, LL, scale);
    gemm_nn(scores, x, bufB, LL, DD, LL, SS, (long)LL * LL, LD, LD);
    gemm_nn(bufB, pre_Wv, bufC, LL, DD, DD, SS, LD, (long)DD * DD, LD);
    ln_kernel<<<SS * LL, 256>>>(x, bufC, ln1_g, ln1_b, bufA, LL, DD);

    // ================= pre_mlp =================
    gemm_nn_bias(bufA, pre_W1, pre_b1, q, LL, DD4, DD, SS, LD, (long)DD * DD4, DD4, LD4, true);
    gemm_nn_bias(q, pre_W2, pre_b2, bufC, LL, DD, DD4, SS, LD4, (long)DD4 * DD, DD, LD, false);
    ln_kernel<<<SS * LL, 256>>>(bufA, bufC, ln4p_g, ln4p_b, bufB, LL, DD);

    // ================= cross_step attention =================
    transpose_kernel<<<SS * LL, 256>>>(bufB, bufA, SS, LL);   // bufA = xt [L,S,D]
    gemm_nn(bufA, cross_Wq, q, LL * SS, DD4, DD, 1, 0, 0, 0);
    gemm_nn(bufA, cross_Wk, k, LL * SS, DD4, DD, 1, 0, 0, 0);
    gemm_nt(q, k, scores, SS, SS, DD4, LL, SD4, SD4, (long)SS * SS);
    softmax_kernel<<<LL * SS, 256>>>(scores, SS, scale);
    gemm_nn(scores, bufA, bufC, SS, DD, SS, LL, (long)SS * SS, SD, SD);
    gemm_nn(bufC, cross_Wv, bufB, LL * SS, DD, DD, 1, 0, 0, 0); // bufB = h [L,S,D]
    ln_kernel<<<LL * SS, 256>>>(bufA, bufB, ln2_g, ln2_b, bufC, 1, 0);
    transpose_kernel<<<LL * SS, 256>>>(bufC, bufA, LL, SS);   // bufA = x [S,L,D]

    // ================= post_self_step attention =================
    gemm_nn(bufA, post_Wq, q, LL, DD4, DD, SS, LD, (long)DD * DD4, LD4);
    gemm_nn(bufA, post_Wk, k, LL, DD4, DD, SS, LD, (long)DD * DD4, LD4);
    gemm_nt(q, k, scores, LL, LL, DD4, SS, LD4, LD4, (long)LL * LL);
    softmax_kernel<<<SS * LL, 256>>>(scores, LL, scale);
    gemm_nn(scores, bufA, bufB, LL, DD, LL, SS, (long)LL * LL, LD, LD);
    gemm_nn(bufB, post_Wv, bufC, LL, DD, DD, SS, LD, (long)DD * DD, LD);
    ln_kernel<<<SS * LL, 256>>>(bufA, bufC, ln3_g, ln3_b, bufB, LL, DD);

    // ================= post_mlp =================
    gemm_nn_bias(bufB, post_W1, post_b1, q, LL, DD4, DD, SS, LD, (long)DD * DD4, DD4, LD4, true);
    gemm_nn_bias(q, post_W2, post_b2, bufC, LL, DD, DD4, SS, LD4, (long)DD4 * DD, DD, LD, false);
    ln_kernel<<<SS * LL, 256>>>(bufB, bufC, ln4_g, ln4_b, out, LL, DD);
}

// round 2
// speedup vs baseline: 1.0017x; 1.0017x over previous
#include <cuda_runtime.h>
#include <math.h>

// Problem dims
#define SS 50
#define LL 1024
#define DD 768
#define DD4 192

// ---------------- static scratch (alloc-free rule) ----------------
__device__ float g_bufA[(size_t)SS * LL * DD];
__device__ float g_bufB[(size_t)SS * LL * DD];
__device__ float g_bufC[(size_t)SS * LL * DD];
__device__ float g_q[(size_t)SS * LL * DD4];
__device__ float g_k[(size_t)SS * LL * DD4];
__device__ float g_scores[(size_t)SS * LL * LL];

// ---------------- generic tiled SGEMM ----------------
// C[b] = A[b] @ B[b] (+bias[b]) (+relu)
// A: [M,K] row-major. B: NN -> [K,N]; NT -> [N,K] (computes A @ B^T).
// Per-batch element strides sA, sB, sBias, sC.
template<bool TRANSB, bool BIAS, bool RELU>
__global__ __launch_bounds__(256)
void sgemm_kernel(const float* __restrict__ Ab, const float* __restrict__ Bb,
                  const float* __restrict__ biasb, float* __restrict__ Cb,
                  int M, int N, int K,
                  long sA, long sB, long sBias, long sC)
{
    const int BM = 128, BN = 128, BK = 8, TM = 8, TN = 8;
    __shared__ float As[BK][BM];
    __shared__ float Bs[BK][BN];

    const int b = blockIdx.z;
    const float* A = Ab + (long)b * sA;
    const float* B = Bb + (long)b * sB;
    float* C = Cb + (long)b * sC;

    const int block_row = blockIdx.y * BM;
    const int block_col = blockIdx.x * BN;
    const int tid = threadIdx.x;          // 256 threads
    const int tr = tid / 16;              // 0..15
    const int tc = tid % 16;              // 0..15

    float acc[TM][TN];
    #pragma unroll
    for (int i = 0; i < TM; i++)
        #pragma unroll
        for (int j = 0; j < TN; j++)
            acc[i][j] = 0.0f;

    float ra[TM], rb[TN];

    for (int k0 = 0; k0 < K; k0 += BK) {
        // Load A tile: BM x BK = 1024 elems, 4 per thread
        #pragma unroll
        for (int i = 0; i < 4; i++) {
            int idx = tid + i * 256;
            int r = idx / BK, c = idx % BK;
            int gr = block_row + r, gc = k0 + c;
            As[c][r] = (gr < M && gc < K) ? A[(long)gr * K + gc] : 0.0f;
        }
        // Load B tile: BK x BN = 1024 elems, 4 per thread
        if (TRANSB) {
            #pragma unroll
            for (int i = 0; i < 4; i++) {
                int idx = tid + i * 256;
                int n = idx / BK, kk = idx % BK;   // contiguous kk -> coalesced-ish
                int gn = block_col + n, gk = k0 + kk;
                Bs[kk][n] = (gn < N && gk < K) ? B[(long)gn * K + gk] : 0.0f;
            }
        } else {
            #pragma unroll
            for (int i = 0; i < 4; i++) {
                int idx = tid + i * 256;
                int r = idx / BN, c = idx % BN;
                int gk = k0 + r, gn = block_col + c;
                Bs[r][c] = (gk < K && gn < N) ? B[(long)gk * N + gn] : 0.0f;
            }
        }
        __syncthreads();

        #pragma unroll
        for (int kk = 0; kk < BK; kk++) {
            #pragma unroll
            for (int i = 0; i < TM; i++) ra[i] = As[kk][tr * TM + i];
            #pragma unroll
            for (int j = 0; j < TN; j++) rb[j] = Bs[kk][tc * TN + j];
            #pragma unroll
            for (int i = 0; i < TM; i++)
                #pragma unroll
                for (int j = 0; j < TN; j++)
                    acc[i][j] += ra[i] * rb[j];
        }
        __syncthreads();
    }

    #pragma unroll
    for (int i = 0; i < TM; i++) {
        int gm = block_row + tr * TM + i;
        if (gm >= M) continue;
        #pragma unroll
        for (int j = 0; j < TN; j++) {
            int gn = block_col + tc * TN + j;
            if (gn >= N) continue;
            float v = acc[i][j];
            if (BIAS) v += biasb[(long)b * sBias + gn];
            if (RELU) v = fmaxf(v, 0.0f);
            C[(long)gm * N + gn] = v;
        }
    }
}

// ---------------- row softmax (with pre-scale), rows up to 1024 ----------------
__global__ __launch_bounds__(256)
void softmax_kernel(float* __restrict__ data, int n, float scale)
{
    long row = blockIdx.x;
    float* p = data + row * (long)n;
    int t = threadIdx.x;
    int w = t >> 5, lane = t & 31;

    float loc[4];
    int cnt = 0;
    float mx = -3.0e38f;
    for (int i = t; i < n; i += 256) {
        float v = p[i] * scale;
        loc[cnt++] = v;
        mx = fmaxf(mx, v);
    }
    // block max
    #pragma unroll
    for (int o = 16; o > 0; o >>= 1) mx = fmaxf(mx, __shfl_xor_sync(0xffffffffu, mx, o));
    __shared__ float red[8];
    if (lane == 0) red[w] = mx;
    __syncthreads();
    if (t < 8) {
        float v = red[t];
        #pragma unroll
        for (int o = 4; o > 0; o >>= 1) v = fmaxf(v, __shfl_xor_sync(0xffu, v, o));
        if (t == 0) red[0] = v;
    }
    __syncthreads();
    mx = red[0];
    __syncthreads();

    float sum = 0.0f;
    for (int c = 0; c < cnt; c++) {
        float e = __expf(loc[c] - mx);
        loc[c] = e;
        sum += e;
    }
    #pragma unroll
    for (int o = 16; o > 0; o >>= 1) sum += __shfl_xor_sync(0xffffffffu, sum, o);
    if (lane == 0) red[w] = sum;
    __syncthreads();
    if (t < 8) {
        float v = red[t];
        #pragma unroll
        for (int o = 4; o > 0; o >>= 1) v += __shfl_xor_sync(0xffu, v, o);
        if (t == 0) red[0] = v;
    }
    __syncthreads();
    float inv = 1.0f / red[0];

    cnt = 0;
    for (int i = t; i < n; i += 256) p[i] = loc[cnt++] * inv;
}

// ---------------- fused residual + LayerNorm over D=768 ----------------
// out[row] = LN(resid[row] + h[row]) * gamma + beta,
// gamma/beta selected by group: offset = (row / rows_per_group) * gstride.
__global__ __launch_bounds__(256)
void ln_kernel(const float* __restrict__ resid, const float* __restrict__ h,
               const float* __restrict__ gam, const float* __restrict__ bet,
               float* __restrict__ out, int rows_per_group, int gstride)
{
    long row = blockIdx.x;
    const float* r  = resid + row * (long)DD;
    const float* hh = h     + row * (long)DD;
    long go = (long)(row / rows_per_group) * gstride;
    const float* gp = gam + go;
    const float* bp = bet + go;
    int t = threadIdx.x;
    int w = t >> 5, lane = t & 31;

    float v[3];
    float s = 0.0f, s2 = 0.0f;
    #pragma unroll
    for (int i = 0; i < 3; i++) {
        int d = t + i * 256;
        float val = r[d] + hh[d];
        v[i] = val;
        s += val;
        s2 += val * val;
    }
    #pragma unroll
    for (int o = 16; o > 0; o >>= 1) {
        s  += __shfl_xor_sync(0xffffffffu, s, o);
        s2 += __shfl_xor_sync(0xffffffffu, s2, o);
    }
    __shared__ float rs[8], rs2[8];
    if (lane == 0) { rs[w] = s; rs2[w] = s2; }
    __syncthreads();
    if (t < 8) {
        s = rs[t]; s2 = rs2[t];
        #pragma unroll
        for (int o = 4; o > 0; o >>= 1) {
            s  += __shfl_xor_sync(0xffu, s, o);
            s2 += __shfl_xor_sync(0xffu, s2, o);
        }
        if (t == 0) { rs[0] = s; rs2[0] = s2; }
    }
    __syncthreads();
    float mean = rs[0] * (1.0f / DD);
    float var  = rs2[0] * (1.0f / DD) - mean * mean;
    float inv  = rsqrtf(var + 1e-5f);

    float* op = out + row * (long)DD;
    #pragma unroll
    for (int i = 0; i < 3; i++) {
        int d = t + i * 256;
        op[d] = (v[i] - mean) * inv * gp[d] + bp[d];
    }
}

// ---------------- transpose [d0, d1, D] -> [d1, d0, D] ----------------
__global__ __launch_bounds__(256)
void transpose_kernel(const float* __restrict__ in, float* __restrict__ out,
                      int d0, int d1)
{
    long blk = blockIdx.x;
    int i = (int)(blk / d1);
    int j = (int)(blk % d1);
    const float* src = in + ((long)i * d1 + j) * DD;
    float* dst = out + ((long)j * d0 + i) * DD;
    for (int t = threadIdx.x; t < DD; t += 256) dst[t] = src[t];
}

// ---------------- launch plumbing ----------------
static inline int cdiv(int a, int b) { return (a + b - 1) / b; }

static void gemm_nn(const float* A, const float* B, float* C,
                    int M, int N, int K, int batch,
                    long sA, long sB, long sC)
{
    dim3 grid(cdiv(N, 128), cdiv(M, 128), batch);
    sgemm_kernel<false, false, false><<<grid, 256>>>(A, B, nullptr, C, M, N, K, sA, sB, 0, sC);
}
static void gemm_nt(const float* A, const float* B, float* C,
                    int M, int N, int K, int batch,
                    long sA, long sB, long sC)
{
    dim3 grid(cdiv(N, 128), cdiv(M, 128), batch);
    sgemm_kernel<true, false, false><<<grid, 256>>>(A, B, nullptr, C, M, N, K, sA, sB, 0, sC);
}
static void gemm_nn_bias(const float* A, const float* B, const float* bias, float* C,
                         int M, int N, int K, int batch,
                         long sA, long sB, long sBias, long sC, bool relu)
{
    dim3 grid(cdiv(N, 128), cdiv(M, 128), batch);
    if (relu)
        sgemm_kernel<false, true, true><<<grid, 256>>>(A, B, bias, C, M, N, K, sA, sB, sBias, sC);
    else
        sgemm_kernel<false, true, false><<<grid, 256>>>(A, B, bias, C, M, N, K, sA, sB, sBias, sC);
}

extern "C" void kernel_launch(void* const* d_in, const int* in_sizes, int n_in,
                              void* d_out, int out_size)
{
    (void)in_sizes; (void)n_in; (void)out_size;

    const float* x        = (const float*)d_in[0];
    const float* pre_Wq   = (const float*)d_in[1];
    const float* pre_Wk   = (const float*)d_in[2];
    const float* pre_Wv   = (const float*)d_in[3];
    const float* ln1_g    = (const float*)d_in[4];
    const float* ln1_b    = (const float*)d_in[5];
    const float* pre_W1   = (const float*)d_in[6];
    const float* pre_b1   = (const float*)d_in[7];
    const float* pre_W2   = (const float*)d_in[8];
    const float* pre_b2   = (const float*)d_in[9];
    const float* ln4p_g   = (const float*)d_in[10];
    const float* ln4p_b   = (const float*)d_in[11];
    const float* cross_Wq = (const float*)d_in[12];
    const float* cross_Wk = (const float*)d_in[13];
    const float* cross_Wv = (const float*)d_in[14];
    const float* ln2_g    = (const float*)d_in[15];
    const float* ln2_b    = (const float*)d_in[16];
    const float* post_Wq  = (const float*)d_in[17];
    const float* post_Wk  = (const float*)d_in[18];
    const float* post_Wv  = (const float*)d_in[19];
    const float* ln3_g    = (const float*)d_in[20];
    const float* ln3_b    = (const float*)d_in[21];
    const float* post_W1  = (const float*)d_in[22];
    const float* post_b1  = (const float*)d_in[23];
    const float* post_W2  = (const float*)d_in[24];
    const float* post_b2  = (const float*)d_in[25];
    const float* ln4_g    = (const float*)d_in[26];
    const float* ln4_b    = (const float*)d_in[27];
    float* out = (float*)d_out;

    float *bufA, *bufB, *bufC, *q, *k, *scores;
    cudaGetSymbolAddress((void**)&bufA, g_bufA);
    cudaGetSymbolAddress((void**)&bufB, g_bufB);
    cudaGetSymbolAddress((void**)&bufC, g_bufC);
    cudaGetSymbolAddress((void**)&q, g_q);
    cudaGetSymbolAddress((void**)&k, g_k);
    cudaGetSymbolAddress((void**)&scores, g_scores);

    const float scale = 1.0f / sqrtf((float)DD4);
    const long LD  = (long)LL * DD;
    const long LD4 = (long)LL * DD4;
    const long SD  = (long)SS * DD;
    const long SD4 = (long)SS * DD4;

    // ================= pre_self_step attention =================
    gemm_nn(x, pre_Wq, q, LL, DD4, DD, SS, LD, (long)DD * DD4, LD4);
    gemm_nn(x, pre_Wk, k, LL, DD4, DD, SS, LD, (long)DD * DD4, LD4);
    gemm_nt(q, k, scores, LL, LL, DD4, SS, LD4, LD4, (long)LL * LL);
    softmax_kernel<<<SS * LL, 256>>>(scores, LL, scale);
    gemm_nn(scores, x, bufB, LL, DD, LL, SS, (long)LL * LL, LD, LD);
    gemm_nn(bufB, pre_Wv, bufC, LL, DD, DD, SS, LD, (long)DD * DD, LD);
    ln_kernel<<<SS * LL, 256>>>(x, bufC, ln1_g, ln1_b, bufA, LL, DD);

    // ================= pre_mlp =================
    gemm_nn_bias(bufA, pre_W1, pre_b1, q, LL, DD4, DD, SS, LD, (long)DD * DD4, DD4, LD4, true);
    gemm_nn_bias(q, pre_W2, pre_b2, bufC, LL, DD, DD4, SS, LD4, (long)DD4 * DD, DD, LD, false);
    ln_kernel<<<SS * LL, 256>>>(bufA, bufC, ln4p_g, ln4p_b, bufB, LL, DD);

    // ================= cross_step attention =================
    transpose_kernel<<<SS * LL, 256>>>(bufB, bufA, SS, LL);   // bufA = xt [L,S,D]
    gemm_nn(bufA, cross_Wq, q, LL * SS, DD4, DD, 1, 0, 0, 0);
    gemm_nn(bufA, cross_Wk, k, LL * SS, DD4, DD, 1, 0, 0, 0);
    gemm_nt(q, k, scores, SS, SS, DD4, LL, SD4, SD4, (long)SS * SS);
    softmax_kernel<<<LL * SS, 256>>>(scores, SS, scale);
    gemm_nn(scores, bufA, bufC, SS, DD, SS, LL, (long)SS * SS, SD, SD);
    gemm_nn(bufC, cross_Wv, bufB, LL * SS, DD, DD, 1, 0, 0, 0); // bufB = h [L,S,D]
    ln_kernel<<<LL * SS, 256>>>(bufA, bufB, ln2_g, ln2_b, bufC, 1, 0);
    transpose_kernel<<<LL * SS, 256>>>(bufC, bufA, LL, SS);   // bufA = x [S,L,D]

    // ================= post_self_step attention =================
    gemm_nn(bufA, post_Wq, q, LL, DD4, DD, SS, LD, (long)DD * DD4, LD4);
    gemm_nn(bufA, post_Wk, k, LL, DD4, DD, SS, LD, (long)DD * DD4, LD4);
    gemm_nt(q, k, scores, LL, LL, DD4, SS, LD4, LD4, (long)LL * LL);
    softmax_kernel<<<SS * LL, 256>>>(scores, LL, scale);
    gemm_nn(scores, bufA, bufB, LL, DD, LL, SS, (long)LL * LL, LD, LD);
    gemm_nn(bufB, post_Wv, bufC, LL, DD, DD, SS, LD, (long)DD * DD, LD);
    ln_kernel<<<SS * LL, 256>>>(bufA, bufC, ln3_g, ln3_b, bufB, LL, DD);

    // ================= post_mlp =================
    gemm_nn_bias(bufB, post_W1, post_b1, q, LL, DD4, DD, SS, LD, (long)DD * DD4, DD4, LD4, true);
    gemm_nn_bias(q, post_W2, post_b2, bufC, LL, DD, DD4, SS, LD4, (long)DD4 * DD, DD, LD, false);
    ln_kernel<<<SS * LL, 256>>>(bufB, bufC, ln4_g, ln4_b, out, LL, DD);
}

// round 3
// speedup vs baseline: 2.7059x; 2.7015x over previous
#include <cuda_runtime.h>
#include <math.h>
#include <stdint.h>

// Problem dims
#define SS 50
#define LL 1024
#define DD 768
#define DD4 192

// ---------------- static scratch (alloc-free rule) ----------------
__device__ float g_bufA[(size_t)SS * LL * DD];
__device__ float g_bufB[(size_t)SS * LL * DD];
__device__ float g_bufC[(size_t)SS * LL * DD];
__device__ float g_q[(size_t)SS * LL * DD4];
__device__ float g_k[(size_t)SS * LL * DD4];
__device__ float g_scores[(size_t)SS * LL * LL];

// =================================================================
// TF32 tensor-core GEMM (mma.sync m16n8k8)
// C[b] = A[b] @ B[b] (+bias) (+relu)
// A: [M,K] row-major. NN: B [K,N]; NT: B [N,K] (C = A @ B^T).
// Requires K % 16 == 0, pointers 16B aligned, N % 4 == 0.
// =================================================================

__device__ __forceinline__ uint32_t f2tf(float f) {
    uint32_t r;
    asm("cvt.rna.tf32.f32 %0, %1;" : "=r"(r) : "f"(f));
    return r;
}

__device__ __forceinline__ void mma_tf32(float* d, const uint32_t* a, const uint32_t* b) {
    asm volatile(
        "mma.sync.aligned.m16n8k8.row.col.f32.tf32.tf32.f32 "
        "{%0,%1,%2,%3}, {%4,%5,%6,%7}, {%8,%9}, {%0,%1,%2,%3};\n"
        : "+f"(d[0]), "+f"(d[1]), "+f"(d[2]), "+f"(d[3])
        : "r"(a[0]), "r"(a[1]), "r"(a[2]), "r"(a[3]),
          "r"(b[0]), "r"(b[1]));
}

// A smem: [128 rows][stride 20]  (pad 4: conflict-free for frag loads, 16B-aligned rows)
// B smem NT: same layout as A ([n][k], stride 20)
// B smem NN: [16 k][stride 132]  (2-way conflicts on frag loads, acceptable)
#define AS_STRIDE 20
#define BS_STRIDE_NN 132

template<bool TRANSB, bool BIAS, bool RELU>
__global__ __launch_bounds__(256, 2)
void tf32_gemm_kernel(const float* __restrict__ Ab, const float* __restrict__ Bb,
                      const float* __restrict__ biasb, float* __restrict__ Cb,
                      int M, int N, int K,
                      long sA, long sB, long sBias, long sC)
{
    __shared__ uint32_t As[128 * AS_STRIDE];
    __shared__ uint32_t Bs[128 * AS_STRIDE];   // max(128*20, 16*132)

    const int b = blockIdx.z;
    const float* A = Ab + (long)b * sA;
    const float* B = Bb + (long)b * sB;
    float* C = Cb + (long)b * sC;

    const int brow = blockIdx.y * 128;
    const int bcol = blockIdx.x * 128;
    const int tid = threadIdx.x;
    const int wid = tid >> 5;
    const int lane = tid & 31;
    const int g = lane >> 2;     // 0..7
    const int c = lane & 3;      // 0..3
    const int warp_m = (wid & 1) * 64;   // 4 m16 atoms
    const int warp_n = (wid >> 1) * 32;  // 4 n8 atoms

    float acc[4][4][4];
    #pragma unroll
    for (int i = 0; i < 4; i++)
        #pragma unroll
        for (int j = 0; j < 4; j++)
            #pragma unroll
            for (int r = 0; r < 4; r++)
                acc[i][j][r] = 0.0f;

    for (int k0 = 0; k0 < K; k0 += 16) {
        // ---- stage A: 128x16, 2 float4 per thread ----
        #pragma unroll
        for (int i = 0; i < 2; i++) {
            int idx = tid + i * 256;
            int r = idx >> 2;
            int kq = (idx & 3) << 2;
            int gr = brow + r;
            float4 v = make_float4(0.f, 0.f, 0.f, 0.f);
            if (gr < M) v = *(const float4*)&A[(long)gr * K + k0 + kq];
            uint32_t* p = &As[r * AS_STRIDE + kq];
            p[0] = f2tf(v.x); p[1] = f2tf(v.y); p[2] = f2tf(v.z); p[3] = f2tf(v.w);
        }
        // ---- stage B ----
        if (TRANSB) {
            #pragma unroll
            for (int i = 0; i < 2; i++) {
                int idx = tid + i * 256;
                int r = idx >> 2;            // n
                int kq = (idx & 3) << 2;
                int gn = bcol + r;
                float4 v = make_float4(0.f, 0.f, 0.f, 0.f);
                if (gn < N) v = *(const float4*)&B[(long)gn * K + k0 + kq];
                uint32_t* p = &Bs[r * AS_STRIDE + kq];
                p[0] = f2tf(v.x); p[1] = f2tf(v.y); p[2] = f2tf(v.z); p[3] = f2tf(v.w);
            }
        } else {
            #pragma unroll
            for (int i = 0; i < 2; i++) {
                int idx = tid + i * 256;
                int kk = idx >> 5;           // 0..15
                int nq = (idx & 31) << 2;    // 0..124
                int gn = bcol + nq;
                float4 v = make_float4(0.f, 0.f, 0.f, 0.f);
                if (gn < N) v = *(const float4*)&B[(long)(k0 + kk) * N + gn];
                uint32_t* p = &Bs[kk * BS_STRIDE_NN + nq];
                p[0] = f2tf(v.x); p[1] = f2tf(v.y); p[2] = f2tf(v.z); p[3] = f2tf(v.w);
            }
        }
        __syncthreads();

        // ---- compute: two k8 steps ----
        #pragma unroll
        for (int ks = 0; ks < 16; ks += 8) {
            uint32_t af[4][4], bf[4][2];
            #pragma unroll
            for (int am = 0; am < 4; am++) {
                int r0 = warp_m + am * 16 + g;
                af[am][0] = As[r0 * AS_STRIDE + ks + c];
                af[am][1] = As[(r0 + 8) * AS_STRIDE + ks + c];
                af[am][2] = As[r0 * AS_STRIDE + ks + c + 4];
                af[am][3] = As[(r0 + 8) * AS_STRIDE + ks + c + 4];
            }
            #pragma unroll
            for (int bn = 0; bn < 4; bn++) {
                int col = warp_n + bn * 8 + g;
                if (TRANSB) {
                    bf[bn][0] = Bs[col * AS_STRIDE + ks + c];
                    bf[bn][1] = Bs[col * AS_STRIDE + ks + c + 4];
                } else {
                    bf[bn][0] = Bs[(ks + c) * BS_STRIDE_NN + col];
                    bf[bn][1] = Bs[(ks + c + 4) * BS_STRIDE_NN + col];
                }
            }
            #pragma unroll
            for (int am = 0; am < 4; am++)
                #pragma unroll
                for (int bn = 0; bn < 4; bn++)
                    mma_tf32(acc[am][bn], af[am], bf[bn]);
        }
        __syncthreads();
    }

    // ---- epilogue ----
    #pragma unroll
    for (int am = 0; am < 4; am++) {
        int row0 = brow + warp_m + am * 16 + g;
        #pragma unroll
        for (int bn = 0; bn < 4; bn++) {
            int col = bcol + warp_n + bn * 8 + c * 2;
            float v0 = acc[am][bn][0], v1 = acc[am][bn][1];
            float v2 = acc[am][bn][2], v3 = acc[am][bn][3];
            if (BIAS) {
                float b0 = biasb[(long)b * sBias + col];
                float b1 = biasb[(long)b * sBias + col + 1];
                v0 += b0; v1 += b1; v2 += b0; v3 += b1;
            }
            if (RELU) {
                v0 = fmaxf(v0, 0.f); v1 = fmaxf(v1, 0.f);
                v2 = fmaxf(v2, 0.f); v3 = fmaxf(v3, 0.f);
            }
            if (col + 1 < N || col < N) {  // N even; col even => col+1<N iff col<N
                if (col < N) {
                    if (row0 < M)     *(float2*)&C[(long)row0 * N + col]       = make_float2(v0, v1);
                    if (row0 + 8 < M) *(float2*)&C[(long)(row0 + 8) * N + col] = make_float2(v2, v3);
                }
            }
        }
    }
}

// =================================================================
// FFMA fallback SGEMM (used only for the tiny cross-step GEMMs)
// =================================================================
template<bool TRANSB, bool BIAS, bool RELU>
__global__ __launch_bounds__(256)
void sgemm_kernel(const float* __restrict__ Ab, const float* __restrict__ Bb,
                  const float* __restrict__ biasb, float* __restrict__ Cb,
                  int M, int N, int K,
                  long sA, long sB, long sBias, long sC)
{
    const int BM = 128, BN = 128, BK = 8, TM = 8, TN = 8;
    __shared__ float As[BK][BM];
    __shared__ float Bsm[BK][BN];

    const int b = blockIdx.z;
    const float* A = Ab + (long)b * sA;
    const float* B = Bb + (long)b * sB;
    float* C = Cb + (long)b * sC;

    const int block_row = blockIdx.y * BM;
    const int block_col = blockIdx.x * BN;
    const int tid = threadIdx.x;
    const int tr = tid / 16;
    const int tc = tid % 16;

    float acc[TM][TN];
    #pragma unroll
    for (int i = 0; i < TM; i++)
        #pragma unroll
        for (int j = 0; j < TN; j++)
            acc[i][j] = 0.0f;

    float ra[TM], rb[TN];

    for (int k0 = 0; k0 < K; k0 += BK) {
        #pragma unroll
        for (int i = 0; i < 4; i++) {
            int idx = tid + i * 256;
            int r = idx / BK, cc = idx % BK;
            int gr = block_row + r, gc = k0 + cc;
            As[cc][r] = (gr < M && gc < K) ? A[(long)gr * K + gc] : 0.0f;
        }
        if (TRANSB) {
            #pragma unroll
            for (int i = 0; i < 4; i++) {
                int idx = tid + i * 256;
                int n = idx / BK, kk = idx % BK;
                int gn = block_col + n, gk = k0 + kk;
                Bsm[kk][n] = (gn < N && gk < K) ? B[(long)gn * K + gk] : 0.0f;
            }
        } else {
            #pragma unroll
            for (int i = 0; i < 4; i++) {
                int idx = tid + i * 256;
                int r = idx / BN, cc = idx % BN;
                int gk = k0 + r, gn = block_col + cc;
                Bsm[r][cc] = (gk < K && gn < N) ? B[(long)gk * N + gn] : 0.0f;
            }
        }
        __syncthreads();

        #pragma unroll
        for (int kk = 0; kk < BK; kk++) {
            #pragma unroll
            for (int i = 0; i < TM; i++) ra[i] = As[kk][tr * TM + i];
            #pragma unroll
            for (int j = 0; j < TN; j++) rb[j] = Bsm[kk][tc * TN + j];
            #pragma unroll
            for (int i = 0; i < TM; i++)
                #pragma unroll
                for (int j = 0; j < TN; j++)
                    acc[i][j] += ra[i] * rb[j];
        }
        __syncthreads();
    }

    #pragma unroll
    for (int i = 0; i < TM; i++) {
        int gm = block_row + tr * TM + i;
        if (gm >= M) continue;
        #pragma unroll
        for (int j = 0; j < TN; j++) {
            int gn = block_col + tc * TN + j;
            if (gn >= N) continue;
            float v = acc[i][j];
            if (BIAS) v += biasb[(long)b * sBias + gn];
            if (RELU) v = fmaxf(v, 0.0f);
            C[(long)gm * N + gn] = v;
        }
    }
}

// ---------------- row softmax (with pre-scale) ----------------
__global__ __launch_bounds__(256)
void softmax_kernel(float* __restrict__ data, int n, float scale)
{
    long row = blockIdx.x;
    float* p = data + row * (long)n;
    int t = threadIdx.x;
    int w = t >> 5, lane = t & 31;

    float loc[4];
    int cnt = 0;
    float mx = -3.0e38f;
    for (int i = t; i < n; i += 256) {
        float v = p[i] * scale;
        loc[cnt++] = v;
        mx = fmaxf(mx, v);
    }
    #pragma unroll
    for (int o = 16; o > 0; o >>= 1) mx = fmaxf(mx, __shfl_xor_sync(0xffffffffu, mx, o));
    __shared__ float red[8];
    if (lane == 0) red[w] = mx;
    __syncthreads();
    if (t < 8) {
        float v = red[t];
        #pragma unroll
        for (int o = 4; o > 0; o >>= 1) v = fmaxf(v, __shfl_xor_sync(0xffu, v, o));
        if (t == 0) red[0] = v;
    }
    __syncthreads();
    mx = red[0];
    __syncthreads();

    float sum = 0.0f;
    for (int cc = 0; cc < cnt; cc++) {
        float e = __expf(loc[cc] - mx);
        loc[cc] = e;
        sum += e;
    }
    #pragma unroll
    for (int o = 16; o > 0; o >>= 1) sum += __shfl_xor_sync(0xffffffffu, sum, o);
    if (lane == 0) red[w] = sum;
    __syncthreads();
    if (t < 8) {
        float v = red[t];
        #pragma unroll
        for (int o = 4; o > 0; o >>= 1) v += __shfl_xor_sync(0xffu, v, o);
        if (t == 0) red[0] = v;
    }
    __syncthreads();
    float inv = 1.0f / red[0];

    cnt = 0;
    for (int i = t; i < n; i += 256) p[i] = loc[cnt++] * inv;
}

// ---------------- fused residual + LayerNorm over D=768 ----------------
__global__ __launch_bounds__(256)
void ln_kernel(const float* __restrict__ resid, const float* __restrict__ h,
               const float* __restrict__ gam, const float* __restrict__ bet,
               float* __restrict__ out, int rows_per_group, int gstride)
{
    long row = blockIdx.x;
    const float* r  = resid + row * (long)DD;
    const float* hh = h     + row * (long)DD;
    long go = (long)(row / rows_per_group) * gstride;
    const float* gp = gam + go;
    const float* bp = bet + go;
    int t = threadIdx.x;
    int w = t >> 5, lane = t & 31;

    float v[3];
    float s = 0.0f, s2 = 0.0f;
    #pragma unroll
    for (int i = 0; i < 3; i++) {
        int d = t + i * 256;
        float val = r[d] + hh[d];
        v[i] = val;
        s += val;
        s2 += val * val;
    }
    #pragma unroll
    for (int o = 16; o > 0; o >>= 1) {
        s  += __shfl_xor_sync(0xffffffffu, s, o);
        s2 += __shfl_xor_sync(0xffffffffu, s2, o);
    }
    __shared__ float rs[8], rs2[8];
    if (lane == 0) { rs[w] = s; rs2[w] = s2; }
    __syncthreads();
    if (t < 8) {
        s = rs[t]; s2 = rs2[t];
        #pragma unroll
        for (int o = 4; o > 0; o >>= 1) {
            s  += __shfl_xor_sync(0xffu, s, o);
            s2 += __shfl_xor_sync(0xffu, s2, o);
        }
        if (t == 0) { rs[0] = s; rs2[0] = s2; }
    }
    __syncthreads();
    float mean = rs[0] * (1.0f / DD);
    float var  = rs2[0] * (1.0f / DD) - mean * mean;
    float inv  = rsqrtf(var + 1e-5f);

    float* op = out + row * (long)DD;
    #pragma unroll
    for (int i = 0; i < 3; i++) {
        int d = t + i * 256;
        op[d] = (v[i] - mean) * inv * gp[d] + bp[d];
    }
}

// ---------------- transpose [d0, d1, D] -> [d1, d0, D] ----------------
__global__ __launch_bounds__(256)
void transpose_kernel(const float* __restrict__ in, float* __restrict__ out,
                      int d0, int d1)
{
    long blk = blockIdx.x;
    int i = (int)(blk / d1);
    int j = (int)(blk % d1);
    const float* src = in + ((long)i * d1 + j) * DD;
    float* dst = out + ((long)j * d0 + i) * DD;
    for (int t = threadIdx.x; t < DD; t += 256) dst[t] = src[t];
}

// ---------------- launch plumbing ----------------
static inline int cdiv(int a, int b) { return (a + b - 1) / b; }

// TF32 path (K % 16 == 0 required)
static void tgemm_nn(const float* A, const float* B, float* C,
                     int M, int N, int K, int batch, long sA, long sB, long sC)
{
    dim3 grid(cdiv(N, 128), cdiv(M, 128), batch);
    tf32_gemm_kernel<false, false, false><<<grid, 256>>>(A, B, nullptr, C, M, N, K, sA, sB, 0, sC);
}
static void tgemm_nt(const float* A, const float* B, float* C,
                     int M, int N, int K, int batch, long sA, long sB, long sC)
{
    dim3 grid(cdiv(N, 128), cdiv(M, 128), batch);
    tf32_gemm_kernel<true, false, false><<<grid, 256>>>(A, B, nullptr, C, M, N, K, sA, sB, 0, sC);
}
static void tgemm_nn_bias(const float* A, const float* B, const float* bias, float* C,
                          int M, int N, int K, int batch,
                          long sA, long sB, long sBias, long sC, bool relu)
{
    dim3 grid(cdiv(N, 128), cdiv(M, 128), batch);
    if (relu)
        tf32_gemm_kernel<false, true, true><<<grid, 256>>>(A, B, bias, C, M, N, K, sA, sB, sBias, sC);
    else
        tf32_gemm_kernel<false, true, false><<<grid, 256>>>(A, B, bias, C, M, N, K, sA, sB, sBias, sC);
}

// FFMA path (small cross-step GEMMs)
static void gemm_nn_f(const float* A, const float* B, float* C,
                      int M, int N, int K, int batch, long sA, long sB, long sC)
{
    dim3 grid(cdiv(N, 128), cdiv(M, 128), batch);
    sgemm_kernel<false, false, false><<<grid, 256>>>(A, B, nullptr, C, M, N, K, sA, sB, 0, sC);
}
static void gemm_nt_f(const float* A, const float* B, float* C,
                      int M, int N, int K, int batch, long sA, long sB, long sC)
{
    dim3 grid(cdiv(N, 128), cdiv(M, 128), batch);
    sgemm_kernel<true, false, false><<<grid, 256>>>(A, B, nullptr, C, M, N, K, sA, sB, 0, sC);
}

extern "C" void kernel_launch(void* const* d_in, const int* in_sizes, int n_in,
                              void* d_out, int out_size)
{
    (void)in_sizes; (void)n_in; (void)out_size;

    const float* x        = (const float*)d_in[0];
    const float* pre_Wq   = (const float*)d_in[1];
    const float* pre_Wk   = (const float*)d_in[2];
    const float* pre_Wv   = (const float*)d_in[3];
    const float* ln1_g    = (const float*)d_in[4];
    const float* ln1_b    = (const float*)d_in[5];
    const float* pre_W1   = (const float*)d_in[6];
    const float* pre_b1   = (const float*)d_in[7];
    const float* pre_W2   = (const float*)d_in[8];
    const float* pre_b2   = (const float*)d_in[9];
    const float* ln4p_g   = (const float*)d_in[10];
    const float* ln4p_b   = (const float*)d_in[11];
    const float* cross_Wq = (const float*)d_in[12];
    const float* cross_Wk = (const float*)d_in[13];
    const float* cross_Wv = (const float*)d_in[14];
    const float* ln2_g    = (const float*)d_in[15];
    const float* ln2_b    = (const float*)d_in[16];
    const float* post_Wq  = (const float*)d_in[17];
    const float* post_Wk  = (const float*)d_in[18];
    const float* post_Wv  = (const float*)d_in[19];
    const float* ln3_g    = (const float*)d_in[20];
    const float* ln3_b    = (const float*)d_in[21];
    const float* post_W1  = (const float*)d_in[22];
    const float* post_b1  = (const float*)d_in[23];
    const float* post_W2  = (const float*)d_in[24];
    const float* post_b2  = (const float*)d_in[25];
    const float* ln4_g    = (const float*)d_in[26];
    const float* ln4_b    = (const float*)d_in[27];
    float* out = (float*)d_out;

    float *bufA, *bufB, *bufC, *q, *k, *scores;
    cudaGetSymbolAddress((void**)&bufA, g_bufA);
    cudaGetSymbolAddress((void**)&bufB, g_bufB);
    cudaGetSymbolAddress((void**)&bufC, g_bufC);
    cudaGetSymbolAddress((void**)&q, g_q);
    cudaGetSymbolAddress((void**)&k, g_k);
    cudaGetSymbolAddress((void**)&scores, g_scores);

    const float scale = 1.0f / sqrtf((float)DD4);
    const long LD  = (long)LL * DD;
    const long LD4 = (long)LL * DD4;
    const long SD  = (long)SS * DD;
    const long SD4 = (long)SS * DD4;

    // ================= pre_self_step attention =================
    tgemm_nn(x, pre_Wq, q, LL, DD4, DD, SS, LD, (long)DD * DD4, LD4);
    tgemm_nn(x, pre_Wk, k, LL, DD4, DD, SS, LD, (long)DD * DD4, LD4);
    tgemm_nt(q, k, scores, LL, LL, DD4, SS, LD4, LD4, (long)LL * LL);
    softmax_kernel<<<SS * LL, 256>>>(scores, LL, scale);
    tgemm_nn(scores, x, bufB, LL, DD, LL, SS, (long)LL * LL, LD, LD);
    tgemm_nn(bufB, pre_Wv, bufC, LL, DD, DD, SS, LD, (long)DD * DD, LD);
    ln_kernel<<<SS * LL, 256>>>(x, bufC, ln1_g, ln1_b, bufA, LL, DD);

    // ================= pre_mlp =================
    tgemm_nn_bias(bufA, pre_W1, pre_b1, q, LL, DD4, DD, SS, LD, (long)DD * DD4, DD4, LD4, true);
    tgemm_nn_bias(q, pre_W2, pre_b2, bufC, LL, DD, DD4, SS, LD4, (long)DD4 * DD, DD, LD, false);
    ln_kernel<<<SS * LL, 256>>>(bufA, bufC, ln4p_g, ln4p_b, bufB, LL, DD);

    // ================= cross_step attention =================
    transpose_kernel<<<SS * LL, 256>>>(bufB, bufA, SS, LL);   // bufA = xt [L,S,D]
    tgemm_nn(bufA, cross_Wq, q, LL * SS, DD4, DD, 1, 0, 0, 0);
    tgemm_nn(bufA, cross_Wk, k, LL * SS, DD4, DD, 1, 0, 0, 0);
    gemm_nt_f(q, k, scores, SS, SS, DD4, LL, SD4, SD4, (long)SS * SS);
    softmax_kernel<<<LL * SS, 256>>>(scores, SS, scale);
    gemm_nn_f(scores, bufA, bufC, SS, DD, SS, LL, (long)SS * SS, SD, SD);
    tgemm_nn(bufC, cross_Wv, bufB, LL * SS, DD, DD, 1, 0, 0, 0); // bufB = h [L,S,D]
    ln_kernel<<<LL * SS, 256>>>(bufA, bufB, ln2_g, ln2_b, bufC, 1, 0);
    transpose_kernel<<<LL * SS, 256>>>(bufC, bufA, LL, SS);   // bufA = x [S,L,D]

    // ================= post_self_step attention =================
    tgemm_nn(bufA, post_Wq, q, LL, DD4, DD, SS, LD, (long)DD * DD4, LD4);
    tgemm_nn(bufA, post_Wk, k, LL, DD4, DD, SS, LD, (long)DD * DD4, LD4);
    tgemm_nt(q, k, scores, LL, LL, DD4, SS, LD4, LD4, (long)LL * LL);
    softmax_kernel<<<SS * LL, 256>>>(scores, LL, scale);
    tgemm_nn(scores, bufA, bufB, LL, DD, LL, SS, (long)LL * LL, LD, LD);
    tgemm_nn(bufB, post_Wv, bufC, LL, DD, DD, SS, LD, (long)DD * DD, LD);
    ln_kernel<<<SS * LL, 256>>>(bufA, bufC, ln3_g, ln3_b, bufB, LL, DD);

    // ================= post_mlp =================
    tgemm_nn_bias(bufB, post_W1, post_b1, q, LL, DD4, DD, SS, LD, (long)DD * DD4, DD4, LD4, true);
    tgemm_nn_bias(q, post_W2, post_b2, bufC, LL, DD, DD4, SS, LD4, (long)DD4 * DD, DD, LD, false);
    ln_kernel<<<SS * LL, 256>>>(bufB, bufC, ln4_g, ln4_b, out, LL, DD);
}

// round 4
// speedup vs baseline: 3.1022x; 1.1465x over previous
#include <cuda_runtime.h>
#include <math.h>
#include <stdint.h>

// Problem dims
#define SS 50
#define LL 1024
#define DD 768
#define DD4 192
#define SP 64   // padded step dim for cross attention

// ---------------- static scratch (alloc-free rule) ----------------
__device__ float g_bufA[(size_t)SS * LL * DD];
__device__ float g_bufB[(size_t)SS * LL * DD];
__device__ float g_bufC[(size_t)SS * LL * DD];
__device__ float g_q[(size_t)LL * SP * DD4];     // big enough for padded cross q
__device__ float g_k[(size_t)LL * SP * DD4];
__device__ float g_scores[(size_t)SS * LL * LL]; // doubles as xt_pad [LL,SP,DD] (50.3M <= 52.4M)

// =================================================================
// Pipelined TF32 tensor-core GEMM (mma.sync m16n8k8)
// C[b] = A[b] @ B[b] (+bias) (+relu)
// A: [M,K] row-major (row stride K). NN: B [K,N]; NT: B [N,K] (C = A@B^T).
// Requires K % 16 == 0, N even, 16B-aligned pointers.
// =================================================================

__device__ __forceinline__ uint32_t f2tf(float f) {
    uint32_t r;
    asm("cvt.rna.tf32.f32 %0, %1;" : "=r"(r) : "f"(f));
    return r;
}

__device__ __forceinline__ void mma_tf32(float* d, const uint32_t* a, const uint32_t* b) {
    asm volatile(
        "mma.sync.aligned.m16n8k8.row.col.f32.tf32.tf32.f32 "
        "{%0,%1,%2,%3}, {%4,%5,%6,%7}, {%8,%9}, {%0,%1,%2,%3};\n"
        : "+f"(d[0]), "+f"(d[1]), "+f"(d[2]), "+f"(d[3])
        : "r"(a[0]), "r"(a[1]), "r"(a[2]), "r"(a[3]),
          "r"(b[0]), "r"(b[1]));
}

#define AS_STRIDE 20        // [row][20] padded, conflict-free frag loads
#define BS_NN_STRIDE 132    // [k][132] padded
#define BS_WORDS 2560       // max(128*20, 16*132)

template<bool TRANSB, bool BIAS, bool RELU>
__global__ __launch_bounds__(256, 2)
void tf32_gemm_kernel(const float* __restrict__ Ab, const float* __restrict__ Bb,
                      const float* __restrict__ biasb, float* __restrict__ Cb,
                      int M, int N, int K,
                      long sA, long sB, long sBias, long sC)
{
    __shared__ uint32_t As[2][128 * AS_STRIDE];
    __shared__ uint32_t Bs[2][BS_WORDS];

    const int b = blockIdx.z;
    const float* A = Ab + (long)b * sA;
    const float* B = Bb + (long)b * sB;
    float* C = Cb + (long)b * sC;

    const int brow = blockIdx.y * 128;
    const int bcol = blockIdx.x * 128;
    const int tid = threadIdx.x;
    const int wid = tid >> 5;
    const int lane = tid & 31;
    const int g = lane >> 2;
    const int c = lane & 3;
    const int warp_m = (wid & 1) * 64;
    const int warp_n = (wid >> 1) * 32;

    float acc[4][4][4];
    #pragma unroll
    for (int i = 0; i < 4; i++)
        #pragma unroll
        for (int j = 0; j < 4; j++)
            #pragma unroll
            for (int r = 0; r < 4; r++)
                acc[i][j][r] = 0.0f;

    float4 arg[2], brg[2];
    const float4 z4 = make_float4(0.f, 0.f, 0.f, 0.f);

    // ---- staging lambdas ----
    auto load_regs = [&](int k0) {
        #pragma unroll
        for (int i = 0; i < 2; i++) {
            int idx = tid + i * 256;
            int r = idx >> 2, kq = (idx & 3) << 2;
            int gr = brow + r;
            arg[i] = (gr < M) ? *(const float4*)&A[(long)gr * K + k0 + kq] : z4;
        }
        if (TRANSB) {
            #pragma unroll
            for (int i = 0; i < 2; i++) {
                int idx = tid + i * 256;
                int r = idx >> 2, kq = (idx & 3) << 2;
                int gn = bcol + r;
                brg[i] = (gn < N) ? *(const float4*)&B[(long)gn * K + k0 + kq] : z4;
            }
        } else {
            #pragma unroll
            for (int i = 0; i < 2; i++) {
                int idx = tid + i * 256;
                int kk = idx >> 5, nq = (idx & 31) << 2;
                int gn = bcol + nq;
                brg[i] = (gn < N) ? *(const float4*)&B[(long)(k0 + kk) * N + gn] : z4;
            }
        }
    };
    auto store_smem = [&](int buf) {
        #pragma unroll
        for (int i = 0; i < 2; i++) {
            int idx = tid + i * 256;
            int r = idx >> 2, kq = (idx & 3) << 2;
            uint32_t* p = &As[buf][r * AS_STRIDE + kq];
            p[0] = f2tf(arg[i].x); p[1] = f2tf(arg[i].y);
            p[2] = f2tf(arg[i].z); p[3] = f2tf(arg[i].w);
        }
        if (TRANSB) {
            #pragma unroll
            for (int i = 0; i < 2; i++) {
                int idx = tid + i * 256;
                int r = idx >> 2, kq = (idx & 3) << 2;
                uint32_t* p = &Bs[buf][r * AS_STRIDE + kq];
                p[0] = f2tf(brg[i].x); p[1] = f2tf(brg[i].y);
                p[2] = f2tf(brg[i].z); p[3] = f2tf(brg[i].w);
            }
        } else {
            #pragma unroll
            for (int i = 0; i < 2; i++) {
                int idx = tid + i * 256;
                int kk = idx >> 5, nq = (idx & 31) << 2;
                uint32_t* p = &Bs[buf][kk * BS_NN_STRIDE + nq];
                p[0] = f2tf(brg[i].x); p[1] = f2tf(brg[i].y);
                p[2] = f2tf(brg[i].z); p[3] = f2tf(brg[i].w);
            }
        }
    };

    const int nt = K >> 4;
    load_regs(0);
    store_smem(0);
    __syncthreads();

    for (int t = 0; t < nt; t++) {
        int cur = t & 1;
        bool has_next = (t + 1 < nt);
        if (has_next) load_regs((t + 1) << 4);

        #pragma unroll
        for (int ks = 0; ks < 16; ks += 8) {
            uint32_t af[4][4], bf[4][2];
            #pragma unroll
            for (int am = 0; am < 4; am++) {
                int r0 = warp_m + am * 16 + g;
                af[am][0] = As[cur][r0 * AS_STRIDE + ks + c];
                af[am][1] = As[cur][(r0 + 8) * AS_STRIDE + ks + c];
                af[am][2] = As[cur][r0 * AS_STRIDE + ks + c + 4];
                af[am][3] = As[cur][(r0 + 8) * AS_STRIDE + ks + c + 4];
            }
            #pragma unroll
            for (int bn = 0; bn < 4; bn++) {
                int col = warp_n + bn * 8 + g;
                if (TRANSB) {
                    bf[bn][0] = Bs[cur][col * AS_STRIDE + ks + c];
                    bf[bn][1] = Bs[cur][col * AS_STRIDE + ks + c + 4];
                } else {
                    bf[bn][0] = Bs[cur][(ks + c) * BS_NN_STRIDE + col];
                    bf[bn][1] = Bs[cur][(ks + c + 4) * BS_NN_STRIDE + col];
                }
            }
            #pragma unroll
            for (int am = 0; am < 4; am++)
                #pragma unroll
                for (int bn = 0; bn < 4; bn++)
                    mma_tf32(acc[am][bn], af[am], bf[bn]);
        }

        if (has_next) store_smem(cur ^ 1);
        __syncthreads();
    }

    // ---- epilogue ----
    #pragma unroll
    for (int am = 0; am < 4; am++) {
        int row0 = brow + warp_m + am * 16 + g;
        #pragma unroll
        for (int bn = 0; bn < 4; bn++) {
            int col = bcol + warp_n + bn * 8 + c * 2;
            if (col >= N) continue;           // N even, col even => col+1 < N
            float v0 = acc[am][bn][0], v1 = acc[am][bn][1];
            float v2 = acc[am][bn][2], v3 = acc[am][bn][3];
            if (BIAS) {
                float b0 = biasb[(long)b * sBias + col];
                float b1 = biasb[(long)b * sBias + col + 1];
                v0 += b0; v1 += b1; v2 += b0; v3 += b1;
            }
            if (RELU) {
                v0 = fmaxf(v0, 0.f); v1 = fmaxf(v1, 0.f);
                v2 = fmaxf(v2, 0.f); v3 = fmaxf(v3, 0.f);
            }
            if (row0 < M)     *(float2*)&C[(long)row0 * N + col]       = make_float2(v0, v1);
            if (row0 + 8 < M) *(float2*)&C[(long)(row0 + 8) * N + col] = make_float2(v2, v3);
        }
    }
}

// ---------------- row softmax (pre-scale, padded stride, pad->0) ----------------
__global__ __launch_bounds__(256)
void softmax_kernel(float* __restrict__ data, int n, int stride, float scale)
{
    long row = blockIdx.x;
    float* p = data + row * (long)stride;
    int t = threadIdx.x;
    int w = t >> 5, lane = t & 31;

    float loc[4];
    int cnt = 0;
    float mx = -3.0e38f;
    for (int i = t; i < n; i += 256) {
        float v = p[i] * scale;
        loc[cnt++] = v;
        mx = fmaxf(mx, v);
    }
    #pragma unroll
    for (int o = 16; o > 0; o >>= 1) mx = fmaxf(mx, __shfl_xor_sync(0xffffffffu, mx, o));
    __shared__ float red[8];
    if (lane == 0) red[w] = mx;
    __syncthreads();
    if (t < 8) {
        float v = red[t];
        #pragma unroll
        for (int o = 4; o > 0; o >>= 1) v = fmaxf(v, __shfl_xor_sync(0xffu, v, o));
        if (t == 0) red[0] = v;
    }
    __syncthreads();
    mx = red[0];
    __syncthreads();

    float sum = 0.0f;
    for (int cc = 0; cc < cnt; cc++) {
        float e = __expf(loc[cc] - mx);
        loc[cc] = e;
        sum += e;
    }
    #pragma unroll
    for (int o = 16; o > 0; o >>= 1) sum += __shfl_xor_sync(0xffffffffu, sum, o);
    if (lane == 0) red[w] = sum;
    __syncthreads();
    if (t < 8) {
        float v = red[t];
        #pragma unroll
        for (int o = 4; o > 0; o >>= 1) v += __shfl_xor_sync(0xffu, v, o);
        if (t == 0) red[0] = v;
    }
    __syncthreads();
    float inv = 1.0f / red[0];

    cnt = 0;
    for (int i = t; i < n; i += 256) p[i] = loc[cnt++] * inv;
    for (int i = t; i < stride; i += 256) if (i >= n) p[i] = 0.0f;
}

// ---------------- fused residual + LayerNorm, generalized index mapping ----------
// blockIdx b -> i = b / J, j = b % J.
// resid row = i*ri + j*rj ; h row = i*hi + j*hj ; out row = i*oi + j*oj.
// gamma/beta offset = i * gstride.
__global__ __launch_bounds__(256)
void ln_kernel(const float* __restrict__ resid, const float* __restrict__ h,
               const float* __restrict__ gam, const float* __restrict__ bet,
               float* __restrict__ out, int J,
               long ri, long rj, long hi, long hj, long oi, long oj, long gstride)
{
    long b = blockIdx.x;
    long i = b / J, j = b % J;
    const float* r  = resid + (i * ri + j * rj) * DD;
    const float* hh = h     + (i * hi + j * hj) * DD;
    float* op       = out   + (i * oi + j * oj) * DD;
    const float* gp = gam + i * gstride;
    const float* bp = bet + i * gstride;
    int t = threadIdx.x;
    int w = t >> 5, lane = t & 31;

    float v[3];
    float s = 0.0f, s2 = 0.0f;
    #pragma unroll
    for (int k = 0; k < 3; k++) {
        int d = t + k * 256;
        float val = r[d] + hh[d];
        v[k] = val;
        s += val;
        s2 += val * val;
    }
    #pragma unroll
    for (int o = 16; o > 0; o >>= 1) {
        s  += __shfl_xor_sync(0xffffffffu, s, o);
        s2 += __shfl_xor_sync(0xffffffffu, s2, o);
    }
    __shared__ float rs[8], rs2[8];
    if (lane == 0) { rs[w] = s; rs2[w] = s2; }
    __syncthreads();
    if (t < 8) {
        s = rs[t]; s2 = rs2[t];
        #pragma unroll
        for (int o = 4; o > 0; o >>= 1) {
            s  += __shfl_xor_sync(0xffu, s, o);
            s2 += __shfl_xor_sync(0xffu, s2, o);
        }
        if (t == 0) { rs[0] = s; rs2[0] = s2; }
    }
    __syncthreads();
    float mean = rs[0] * (1.0f / DD);
    float var  = rs2[0] * (1.0f / DD) - mean * mean;
    float inv  = rsqrtf(var + 1e-5f);

    #pragma unroll
    for (int k = 0; k < 3; k++) {
        int d = t + k * 256;
        op[d] = (v[k] - mean) * inv * gp[d] + bp[d];
    }
}

// ---------------- zero the pad rows of xt_pad [LL, SP, DD] ----------------
__global__ __launch_bounds__(256)
void zero_pad_kernel(float* __restrict__ xt)
{
    long idx = (long)blockIdx.x * 256 + threadIdx.x;
    const long per_l = (long)(SP - SS) * DD;     // 14*768 = 10752
    const long total = (long)LL * per_l;
    if (idx >= total) return;
    long l = idx / per_l;
    long off = idx % per_l;
    xt[((long)l * SP + SS) * DD + off] = 0.0f;
}

// ---------------- launch plumbing ----------------
static inline int cdiv(int a, int b) { return (a + b - 1) / b; }

static void tgemm_nn(const float* A, const float* B, float* C,
                     int M, int N, int K, int batch, long sA, long sB, long sC)
{
    dim3 grid(cdiv(N, 128), cdiv(M, 128), batch);
    tf32_gemm_kernel<false, false, false><<<grid, 256>>>(A, B, nullptr, C, M, N, K, sA, sB, 0, sC);
}
static void tgemm_nt(const float* A, const float* B, float* C,
                     int M, int N, int K, int batch, long sA, long sB, long sC)
{
    dim3 grid(cdiv(N, 128), cdiv(M, 128), batch);
    tf32_gemm_kernel<true, false, false><<<grid, 256>>>(A, B, nullptr, C, M, N, K, sA, sB, 0, sC);
}
static void tgemm_nn_bias(const float* A, const float* B, const float* bias, float* C,
                          int M, int N, int K, int batch,
                          long sA, long sB, long sBias, long sC, bool relu)
{
    dim3 grid(cdiv(N, 128), cdiv(M, 128), batch);
    if (relu)
        tf32_gemm_kernel<false, true, true><<<grid, 256>>>(A, B, bias, C, M, N, K, sA, sB, sBias, sC);
    else
        tf32_gemm_kernel<false, true, false><<<grid, 256>>>(A, B, bias, C, M, N, K, sA, sB, sBias, sC);
}

extern "C" void kernel_launch(void* const* d_in, const int* in_sizes, int n_in,
                              void* d_out, int out_size)
{
    (void)in_sizes; (void)n_in; (void)out_size;

    const float* x        = (const float*)d_in[0];
    const float* pre_Wq   = (const float*)d_in[1];
    const float* pre_Wk   = (const float*)d_in[2];
    const float* pre_Wv   = (const float*)d_in[3];
    const float* ln1_g    = (const float*)d_in[4];
    const float* ln1_b    = (const float*)d_in[5];
    const float* pre_W1   = (const float*)d_in[6];
    const float* pre_b1   = (const float*)d_in[7];
    const float* pre_W2   = (const float*)d_in[8];
    const float* pre_b2   = (const float*)d_in[9];
    const float* ln4p_g   = (const float*)d_in[10];
    const float* ln4p_b   = (const float*)d_in[11];
    const float* cross_Wq = (const float*)d_in[12];
    const float* cross_Wk = (const float*)d_in[13];
    const float* cross_Wv = (const float*)d_in[14];
    const float* ln2_g    = (const float*)d_in[15];
    const float* ln2_b    = (const float*)d_in[16];
    const float* post_Wq  = (const float*)d_in[17];
    const float* post_Wk  = (const float*)d_in[18];
    const float* post_Wv  = (const float*)d_in[19];
    const float* ln3_g    = (const float*)d_in[20];
    const float* ln3_b    = (const float*)d_in[21];
    const float* post_W1  = (const float*)d_in[22];
    const float* post_b1  = (const float*)d_in[23];
    const float* post_W2  = (const float*)d_in[24];
    const float* post_b2  = (const float*)d_in[25];
    const float* ln4_g    = (const float*)d_in[26];
    const float* ln4_b    = (const float*)d_in[27];
    float* out = (float*)d_out;

    float *bufA, *bufB, *bufC, *q, *k, *scores;
    cudaGetSymbolAddress((void**)&bufA, g_bufA);
    cudaGetSymbolAddress((void**)&bufB, g_bufB);
    cudaGetSymbolAddress((void**)&bufC, g_bufC);
    cudaGetSymbolAddress((void**)&q, g_q);
    cudaGetSymbolAddress((void**)&k, g_k);
    cudaGetSymbolAddress((void**)&scores, g_scores);
    float* xt_pad = scores;   // non-overlapping lifetime with self-attn scores

    const float scale = 1.0f / sqrtf((float)DD4);
    const long LD  = (long)LL * DD;
    const long LD4 = (long)LL * DD4;

    // ================= pre_self_step attention =================
    tgemm_nn(x, pre_Wq, q, LL, DD4, DD, SS, LD, (long)DD * DD4, LD4);
    tgemm_nn(x, pre_Wk, k, LL, DD4, DD, SS, LD, (long)DD * DD4, LD4);
    tgemm_nt(q, k, scores, LL, LL, DD4, SS, LD4, LD4, (long)LL * LL);
    softmax_kernel<<<SS * LL, 256>>>(scores, LL, LL, scale);
    tgemm_nn(scores, x, bufB, LL, DD, LL, SS, (long)LL * LL, LD, LD);
    tgemm_nn(bufB, pre_Wv, bufC, LL, DD, DD, SS, LD, (long)DD * DD, LD);
    // ln1: rows s*L+l -> same
    ln_kernel<<<SS * LL, 256>>>(x, bufC, ln1_g, ln1_b, bufA, LL, LL, 1, LL, 1, LL, 1, DD);

    // ================= pre_mlp =================
    tgemm_nn_bias(bufA, pre_W1, pre_b1, q, LL, DD4, DD, SS, LD, (long)DD * DD4, DD4, LD4, true);
    tgemm_nn_bias(q, pre_W2, pre_b2, bufC, LL, DD, DD4, SS, LD4, (long)DD4 * DD, DD, LD, false);
    // ln4p fused with transpose into padded layout: out row = l*SP + s  (i=s, j=l)
    ln_kernel<<<SS * LL, 256>>>(bufA, bufC, ln4p_g, ln4p_b, xt_pad, LL, LL, 1, LL, 1, 1, SP, DD);
    zero_pad_kernel<<<cdiv(LL * (SP - SS) * DD, 256), 256>>>(xt_pad);

    // ================= cross_step attention (padded S -> SP) =================
    tgemm_nn(xt_pad, cross_Wq, q, LL * SP, DD4, DD, 1, 0, 0, 0);
    tgemm_nn(xt_pad, cross_Wk, k, LL * SP, DD4, DD, 1, 0, 0, 0);
    // scores per l: [SP, SP], K=192 (pad rows of q/k are zero)
    tgemm_nt(q, k, bufB, SP, SP, DD4, LL, (long)SP * DD4, (long)SP * DD4, (long)SP * SP);
    softmax_kernel<<<LL * SP, 256>>>(bufB, SS, SP, scale);
    // av per l: [SS, DD] = scores[0:50, 0:64] @ xt_pad_l[0:64, :]  (K pads are zero)
    tgemm_nn(bufB, xt_pad, bufC, SS, DD, SP, LL, (long)SP * SP, (long)SP * DD, (long)SS * DD);
    // h = av @ Wv : [LL*SS, DD]
    tgemm_nn(bufC, cross_Wv, bufB, LL * SS, DD, DD, 1, 0, 0, 0);
    // ln2 (shared gamma), fused transpose back: i=l (J=SS), j=s
    // resid row = l*SP+s ; h row = l*SS+s ; out row = s*LL+l
    ln_kernel<<<LL * SS, 256>>>(xt_pad, bufB, ln2_g, ln2_b, bufA, SS, SP, 1, SS, 1, 1, LL, 0);

    // ================= post_self_step attention =================
    tgemm_nn(bufA, post_Wq, q, LL, DD4, DD, SS, LD, (long)DD * DD4, LD4);
    tgemm_nn(bufA, post_Wk, k, LL, DD4, DD, SS, LD, (long)DD * DD4, LD4);
    tgemm_nt(q, k, scores, LL, LL, DD4, SS, LD4, LD4, (long)LL * LL);
    softmax_kernel<<<SS * LL, 256>>>(scores, LL, LL, scale);
    tgemm_nn(scores, bufA, bufB, LL, DD, LL, SS, (long)LL * LL, LD, LD);
    tgemm_nn(bufB, post_Wv, bufC, LL, DD, DD, SS, LD, (long)DD * DD, LD);
    ln_kernel<<<SS * LL, 256>>>(bufA, bufC, ln3_g, ln3_b, bufB, LL, LL, 1, LL, 1, LL, 1, DD);

    // ================= post_mlp =================
    tgemm_nn_bias(bufB, post_W1, post_b1, q, LL, DD4, DD, SS, LD, (long)DD * DD4, DD4, LD4, true);
    tgemm_nn_bias(q, post_W2, post_b2, bufC, LL, DD, DD4, SS, LD4, (long)DD4 * DD, DD, LD, false);
    ln_kernel<<<SS * LL, 256>>>(bufB, bufC, ln4_g, ln4_b, out, LL, LL, 1, LL, 1, LL, 1, DD);
}